// round 4
// baseline (speedup 1.0000x reference)
#include <cuda_runtime.h>

// CapsuleLayer dynamic routing, fully fused. Round 4: interleaved routing chains.
// Shapes: B=64, R=2048, C=16, O=32, I=16. 3 routing iterations.
// Grid: (2048, 2). CTA = 256 threads = 8 warps, owns 32 b's.
// Warp handles 4 b's as 2 f32x2 pairs; the two pairs' routing runs
// instruction-interleaved (2 independent chains) to hide SHFL/MUFU latency.

#define FULLM 0xffffffffu

static __device__ __forceinline__ float2 ffma2(float2 a, float2 b, float2 c) {
    unsigned long long ua = *reinterpret_cast<unsigned long long*>(&a);
    unsigned long long ub = *reinterpret_cast<unsigned long long*>(&b);
    unsigned long long uc = *reinterpret_cast<unsigned long long*>(&c);
    unsigned long long ud;
    asm("fma.rn.f32x2 %0, %1, %2, %3;" : "=l"(ud) : "l"(ua), "l"(ub), "l"(uc));
    return *reinterpret_cast<float2*>(&ud);
}
static __device__ __forceinline__ float2 add2(float2 a, float2 b) {
    unsigned long long ua = *reinterpret_cast<unsigned long long*>(&a);
    unsigned long long ub = *reinterpret_cast<unsigned long long*>(&b);
    unsigned long long ud;
    asm("add.rn.f32x2 %0, %1, %2;" : "=l"(ud) : "l"(ua), "l"(ub));
    return *reinterpret_cast<float2*>(&ud);
}
static __device__ __forceinline__ float2 mul2(float2 a, float2 b) {
    unsigned long long ua = *reinterpret_cast<unsigned long long*>(&a);
    unsigned long long ub = *reinterpret_cast<unsigned long long*>(&b);
    unsigned long long ud;
    asm("mul.rn.f32x2 %0, %1, %2;" : "=l"(ud) : "l"(ua), "l"(ub));
    return *reinterpret_cast<float2*>(&ud);
}
static __device__ __forceinline__ float2 pack2(float x) {
    unsigned long long r;
    asm("mov.b64 %0, {%1, %1};" : "=l"(r) : "f"(x));
    return *reinterpret_cast<float2*>(&r);
}
static __device__ __forceinline__ float rcp_approx(float x) {
    float r; asm("rcp.approx.f32 %0, %1;" : "=f"(r) : "f"(x)); return r;
}
static __device__ __forceinline__ float sqrt_approx(float x) {
    float r; asm("sqrt.approx.f32 %0, %1;" : "=f"(r) : "f"(x)); return r;
}
static __device__ __forceinline__ float2 shfl_xor2(float2 v, int m) {
    v.x = __shfl_xor_sync(FULLM, v.x, m);
    v.y = __shfl_xor_sync(FULLM, v.y, m);
    return v;
}

// squash for BOTH pairs, interleaved: v = s * sqrt(|s|^2)/(1+|s|^2), reduce over o=lanes.
static __device__ __forceinline__ void squash_x2(float2& s0, float2& s1) {
    float2 n0 = mul2(s0, s0);
    float2 n1 = mul2(s1, s1);
#pragma unroll
    for (int m = 16; m >= 1; m >>= 1) {
        n0 = add2(n0, shfl_xor2(n0, m));
        n1 = add2(n1, shfl_xor2(n1, m));
    }
    float f0x = sqrt_approx(n0.x) * rcp_approx(1.0f + n0.x);
    float f0y = sqrt_approx(n0.y) * rcp_approx(1.0f + n0.y);
    float f1x = sqrt_approx(n1.x) * rcp_approx(1.0f + n1.x);
    float f1y = sqrt_approx(n1.y) * rcp_approx(1.0f + n1.y);
    s0 = mul2(s0, make_float2(f0x, f0y));
    s1 = mul2(s1, make_float2(f1x, f1y));
}

// Transpose-reduce for BOTH pairs, interleaved.
// Returns r{q}[lane] = Sum_o S{q}[lane%16][o]*v{q}[o], replicated on both halves.
static __device__ __forceinline__ void tr16_x2(
    const float2* __restrict__ S0, const float2* __restrict__ S1,
    float2 v0, float2 v1, int lane, float2& r0, float2& r1)
{
    const int b0 = lane & 1, b1 = (lane >> 1) & 1, b2 = (lane >> 2) & 1, b3 = (lane >> 3) & 1;
    float2 a0[8], a1[8];
#pragma unroll
    for (int k = 0; k < 8; k++) {
        float2 k0 = mul2(b0 ? S0[2 * k + 1] : S0[2 * k], v0);
        float2 g0 = mul2(b0 ? S0[2 * k] : S0[2 * k + 1], v0);
        float2 k1 = mul2(b0 ? S1[2 * k + 1] : S1[2 * k], v1);
        float2 g1 = mul2(b0 ? S1[2 * k] : S1[2 * k + 1], v1);
        a0[k] = add2(k0, shfl_xor2(g0, 1));
        a1[k] = add2(k1, shfl_xor2(g1, 1));
    }
    float2 c0[4], c1[4];
#pragma unroll
    for (int k = 0; k < 4; k++) {
        float2 k0 = b1 ? a0[2 * k + 1] : a0[2 * k];
        float2 g0 = b1 ? a0[2 * k] : a0[2 * k + 1];
        float2 k1 = b1 ? a1[2 * k + 1] : a1[2 * k];
        float2 g1 = b1 ? a1[2 * k] : a1[2 * k + 1];
        c0[k] = add2(k0, shfl_xor2(g0, 2));
        c1[k] = add2(k1, shfl_xor2(g1, 2));
    }
    float2 d00, d01, d10, d11;
    {
        float2 k0 = b2 ? c0[1] : c0[0];
        float2 g0 = b2 ? c0[0] : c0[1];
        float2 k1 = b2 ? c1[1] : c1[0];
        float2 g1 = b2 ? c1[0] : c1[1];
        d00 = add2(k0, shfl_xor2(g0, 4));
        d10 = add2(k1, shfl_xor2(g1, 4));
        k0 = b2 ? c0[3] : c0[2];
        g0 = b2 ? c0[2] : c0[3];
        k1 = b2 ? c1[3] : c1[2];
        g1 = b2 ? c1[2] : c1[3];
        d01 = add2(k0, shfl_xor2(g0, 4));
        d11 = add2(k1, shfl_xor2(g1, 4));
    }
    float2 e0, e1;
    {
        float2 k0 = b3 ? d01 : d00;
        float2 g0 = b3 ? d00 : d01;
        float2 k1 = b3 ? d11 : d10;
        float2 g1 = b3 ? d10 : d11;
        e0 = add2(k0, shfl_xor2(g0, 8));
        e1 = add2(k1, shfl_xor2(g1, 8));
    }
    e0 = add2(e0, shfl_xor2(e0, 16));
    e1 = add2(e1, shfl_xor2(e1, 16));
    r0 = e0;
    r1 = e1;
}

__global__ void __launch_bounds__(256, 2)
caps_routing_kernel(const float* __restrict__ x,   // [64, 2048, 16]
                    const float* __restrict__ W,   // [2048, 16, 32, 16]
                    float* __restrict__ out)       // [64, 2048, 32]
{
    const int r = blockIdx.x;
    const int b_base = blockIdx.y << 5;   // 0 or 32
    const int tid = threadIdx.x;
    const int lane = tid & 31;   // = o
    const int wid = tid >> 5;    // 0..7

    __shared__ float4 Ws4[4 * 514];          // [i4][c][o] float4, padded
    __shared__ float2 Xs[16 * 16];           // x b-pairs for this CTA's 32 b's
    __shared__ float2 Rbuf[8][2][16];        // per-warp, per-pair route rows

    // ---- stage W[r] (32 KB) with i4-major transpose ----
    {
        const float4* Wg4 = reinterpret_cast<const float4*>(W + (size_t)r * 8192);
#pragma unroll
        for (int k = 0; k < 8; k++) {
            int f = tid + k * 256;
            float4 v = Wg4[f];
            int c = f >> 7, o = (f >> 2) & 31, i4 = f & 3;
            Ws4[i4 * 514 + c * 32 + o] = v;
        }
    }
    // ---- stage x[b_base : b_base+32, r, :] packed as b-pairs ----
    if (tid < 128) {
        int b_loc = tid >> 2, q = tid & 3;
        const float4* xg4 = reinterpret_cast<const float4*>(
            x + (size_t)(b_base + b_loc) * 32768 + (size_t)r * 16);
        float4 xv = xg4[q];
        int p = b_loc >> 1, par = b_loc & 1;
        float* xsf = reinterpret_cast<float*>(Xs);
        xsf[((p * 16 + q * 4 + 0) << 1) + par] = xv.x;
        xsf[((p * 16 + q * 4 + 1) << 1) + par] = xv.y;
        xsf[((p * 16 + q * 4 + 2) << 1) + par] = xv.z;
        xsf[((p * 16 + q * 4 + 3) << 1) + par] = xv.w;
    }
    __syncthreads();

    // ---- u_hat: u[p][c] = f32x2 over local b-pair (wid*2+p), lane = o ----
    float2 u[2][16];
#pragma unroll
    for (int p = 0; p < 2; p++)
#pragma unroll
        for (int c = 0; c < 16; c++) u[p][c] = make_float2(0.f, 0.f);

#pragma unroll
    for (int i4 = 0; i4 < 4; i4++) {
        float2 xv[2][4];
#pragma unroll
        for (int p = 0; p < 2; p++) {
            const float4* xp = reinterpret_cast<const float4*>(&Xs[(wid * 2 + p) * 16 + i4 * 4]);
            float4 q0 = xp[0];
            float4 q1 = xp[1];
            xv[p][0] = make_float2(q0.x, q0.y);
            xv[p][1] = make_float2(q0.z, q0.w);
            xv[p][2] = make_float2(q1.x, q1.y);
            xv[p][3] = make_float2(q1.z, q1.w);
        }
#pragma unroll
        for (int c = 0; c < 16; c++) {
            float4 w4 = Ws4[i4 * 514 + c * 32 + lane];
            float2 w0 = pack2(w4.x), w1 = pack2(w4.y), w2 = pack2(w4.z), w3 = pack2(w4.w);
#pragma unroll
            for (int p = 0; p < 2; p++) {
                u[p][c] = ffma2(w0, xv[p][0], u[p][c]);
                u[p][c] = ffma2(w1, xv[p][1], u[p][c]);
                u[p][c] = ffma2(w2, xv[p][2], u[p][c]);
                u[p][c] = ffma2(w3, xv[p][3], u[p][c]);
            }
        }
    }

    // ---- routing: BOTH pairs interleaved. Iter1 softmax(0)=uniform; final b-update dead. ----
    const float2* S0 = u[0];
    const float2* S1 = u[1];

    // iteration 1: route = 1/16 uniform -> s = mean over c
    float2 s0, s1;
    {
        float2 t0[8], t1[8];
#pragma unroll
        for (int k = 0; k < 8; k++) {
            t0[k] = add2(S0[2 * k], S0[2 * k + 1]);
            t1[k] = add2(S1[2 * k], S1[2 * k + 1]);
        }
        s0 = add2(add2(add2(t0[0], t0[1]), add2(t0[2], t0[3])),
                  add2(add2(t0[4], t0[5]), add2(t0[6], t0[7])));
        s1 = add2(add2(add2(t1[0], t1[1]), add2(t1[2], t1[3])),
                  add2(add2(t1[4], t1[5]), add2(t1[6], t1[7])));
        const float2 k16 = make_float2(0.0625f, 0.0625f);
        s0 = mul2(s0, k16);
        s1 = mul2(s1, k16);
    }

    squash_x2(s0, s1);                 // s -> v (in place)
    float2 bown0, bown1;
    tr16_x2(S0, S1, s0, s1, lane, bown0, bown1);

#pragma unroll
    for (int it = 0; it < 2; it++) {
        // distributed softmax over c for both pairs
        float2 e0 = make_float2(__expf(bown0.x), __expf(bown0.y));
        float2 e1 = make_float2(__expf(bown1.x), __expf(bown1.y));
        float2 Z0 = e0, Z1 = e1;
#pragma unroll
        for (int m = 1; m <= 8; m <<= 1) {
            Z0 = add2(Z0, shfl_xor2(Z0, m));
            Z1 = add2(Z1, shfl_xor2(Z1, m));
        }
        float2 route0 = mul2(e0, make_float2(rcp_approx(Z0.x), rcp_approx(Z0.y)));
        float2 route1 = mul2(e1, make_float2(rcp_approx(Z1.x), rcp_approx(Z1.y)));

        __syncwarp();
        if (lane < 16) {
            Rbuf[wid][0][lane] = route0;
            Rbuf[wid][1][lane] = route1;
        }
        __syncwarp();

        // s{q} = sum_c route{q}[c] * S{q}[c]; routes via uniform float4 broadcasts
        const float4* rb0 = reinterpret_cast<const float4*>(&Rbuf[wid][0][0]);
        const float4* rb1 = reinterpret_cast<const float4*>(&Rbuf[wid][1][0]);
        float2 sa0 = make_float2(0.f, 0.f), sb0 = make_float2(0.f, 0.f);
        float2 sa1 = make_float2(0.f, 0.f), sb1 = make_float2(0.f, 0.f);
#pragma unroll
        for (int j = 0; j < 8; j++) {
            float4 t0 = rb0[j];
            float4 t1 = rb1[j];
            sa0 = ffma2(make_float2(t0.x, t0.y), S0[2 * j + 0], sa0);
            sb0 = ffma2(make_float2(t0.z, t0.w), S0[2 * j + 1], sb0);
            sa1 = ffma2(make_float2(t1.x, t1.y), S1[2 * j + 0], sa1);
            sb1 = ffma2(make_float2(t1.z, t1.w), S1[2 * j + 1], sb1);
        }
        s0 = add2(sa0, sb0);
        s1 = add2(sa1, sb1);

        squash_x2(s0, s1);             // s -> v

        if (it == 0) {
            float2 d0, d1;
            tr16_x2(S0, S1, s0, s1, lane, d0, d1);
            bown0 = add2(bown0, d0);
            bown1 = add2(bown1, d1);
        }
    }

    // ---- write v for all 4 b's: out[b][r][o] ----
    {
        const int bg = b_base + wid * 4;
        float* o0 = out + (size_t)bg * 65536 + (size_t)r * 32 + lane;
        o0[0 * 65536] = s0.x;
        o0[1 * 65536] = s0.y;
        o0[2 * 65536] = s1.x;
        o0[3 * 65536] = s1.y;
    }
}

extern "C" void kernel_launch(void* const* d_in, const int* in_sizes, int n_in,
                              void* d_out, int out_size) {
    const float* x = (const float*)d_in[0];
    const float* W = (const float*)d_in[1];
    // defensive: x is the smaller input (2,097,152 vs 16,777,216 elements)
    if (n_in >= 2 && in_sizes[0] > in_sizes[1]) {
        const float* t = x; x = W; W = t;
    }
    float* out = (float*)d_out;
    dim3 grid(2048, 2);
    caps_routing_kernel<<<grid, 256>>>(x, W, out);
}

// round 5
// speedup vs baseline: 1.5855x; 1.5855x over previous
#include <cuda_runtime.h>

// CapsuleLayer dynamic routing, fully fused. Round 5: c-pair GEMM layout,
// zero pack-MOVs, scalar-b routing chains. Based on R3 (100.8us best).
// Shapes: B=64, R=2048, C=16, O=32, I=16. 3 routing iterations.
// Grid: (2048, 2). CTA = 256 threads = 8 warps, owns 32 b's; warp owns 4 b's.
// Accumulators: S[b][cp] f32x2 over c-pairs (c=2cp, 2cp+1), lane = o.

#define FULLM 0xffffffffu

static __device__ __forceinline__ float2 ffma2(float2 a, float2 b, float2 c) {
    unsigned long long ua = *reinterpret_cast<unsigned long long*>(&a);
    unsigned long long ub = *reinterpret_cast<unsigned long long*>(&b);
    unsigned long long uc = *reinterpret_cast<unsigned long long*>(&c);
    unsigned long long ud;
    asm("fma.rn.f32x2 %0, %1, %2, %3;" : "=l"(ud) : "l"(ua), "l"(ub), "l"(uc));
    return *reinterpret_cast<float2*>(&ud);
}
static __device__ __forceinline__ float2 add2(float2 a, float2 b) {
    unsigned long long ua = *reinterpret_cast<unsigned long long*>(&a);
    unsigned long long ub = *reinterpret_cast<unsigned long long*>(&b);
    unsigned long long ud;
    asm("add.rn.f32x2 %0, %1, %2;" : "=l"(ud) : "l"(ua), "l"(ub));
    return *reinterpret_cast<float2*>(&ud);
}
static __device__ __forceinline__ float2 mul2(float2 a, float2 b) {
    unsigned long long ua = *reinterpret_cast<unsigned long long*>(&a);
    unsigned long long ub = *reinterpret_cast<unsigned long long*>(&b);
    unsigned long long ud;
    asm("mul.rn.f32x2 %0, %1, %2;" : "=l"(ud) : "l"(ua), "l"(ub));
    return *reinterpret_cast<float2*>(&ud);
}
static __device__ __forceinline__ float2 pack2(float x) {
    unsigned long long r;
    asm("mov.b64 %0, {%1, %1};" : "=l"(r) : "f"(x));
    return *reinterpret_cast<float2*>(&r);
}
static __device__ __forceinline__ float rcp_approx(float x) {
    float r; asm("rcp.approx.f32 %0, %1;" : "=f"(r) : "f"(x)); return r;
}
static __device__ __forceinline__ float sqrt_approx(float x) {
    float r; asm("sqrt.approx.f32 %0, %1;" : "=f"(r) : "f"(x)); return r;
}

// squash on 4 independent scalar chains: v[b] = s[b] * sqrt(n)/(1+n), n = sum_o s^2.
static __device__ __forceinline__ void squash4(float* s) {
    float n0 = s[0] * s[0], n1 = s[1] * s[1], n2 = s[2] * s[2], n3 = s[3] * s[3];
#pragma unroll
    for (int m = 16; m >= 1; m >>= 1) {
        n0 += __shfl_xor_sync(FULLM, n0, m);
        n1 += __shfl_xor_sync(FULLM, n1, m);
        n2 += __shfl_xor_sync(FULLM, n2, m);
        n3 += __shfl_xor_sync(FULLM, n3, m);
    }
    s[0] *= sqrt_approx(n0) * rcp_approx(1.0f + n0);
    s[1] *= sqrt_approx(n1) * rcp_approx(1.0f + n1);
    s[2] *= sqrt_approx(n2) * rcp_approx(1.0f + n2);
    s[3] *= sqrt_approx(n3) * rcp_approx(1.0f + n3);
}

// Transpose-reduce for TWO b's (interleaved, bounded live regs).
// A,B: 8 c-pair f32x2 accumulators each (c=2k,2k+1 in halves).
// Returns r{A,B}[lane] = Sum_o u[lane%16][o]*v[o] for each b, replicated halves.
static __device__ __forceinline__ void tr16_pair(
    const float2* __restrict__ A, const float2* __restrict__ B,
    float va, float vb, int lane, float& ra, float& rb)
{
    const int p0 = lane & 1, p1 = (lane >> 1) & 1, p2 = (lane >> 2) & 1, p3 = (lane >> 3) & 1;
    const float2 va2 = pack2(va), vb2 = pack2(vb);
    float aA[8], aB[8];
#pragma unroll
    for (int k = 0; k < 8; k++) {
        float2 tA = mul2(A[k], va2);
        float2 tB = mul2(B[k], vb2);
        float kA = p0 ? tA.y : tA.x, gA = p0 ? tA.x : tA.y;
        float kB = p0 ? tB.y : tB.x, gB = p0 ? tB.x : tB.y;
        aA[k] = kA + __shfl_xor_sync(FULLM, gA, 1);
        aB[k] = kB + __shfl_xor_sync(FULLM, gB, 1);
    }
    float cA[4], cB[4];
#pragma unroll
    for (int k = 0; k < 4; k++) {
        float kA = p1 ? aA[2 * k + 1] : aA[2 * k], gA = p1 ? aA[2 * k] : aA[2 * k + 1];
        float kB = p1 ? aB[2 * k + 1] : aB[2 * k], gB = p1 ? aB[2 * k] : aB[2 * k + 1];
        cA[k] = kA + __shfl_xor_sync(FULLM, gA, 2);
        cB[k] = kB + __shfl_xor_sync(FULLM, gB, 2);
    }
    float dA0, dA1, dB0, dB1;
    {
        float kA = p2 ? cA[1] : cA[0], gA = p2 ? cA[0] : cA[1];
        float kB = p2 ? cB[1] : cB[0], gB = p2 ? cB[0] : cB[1];
        dA0 = kA + __shfl_xor_sync(FULLM, gA, 4);
        dB0 = kB + __shfl_xor_sync(FULLM, gB, 4);
        kA = p2 ? cA[3] : cA[2]; gA = p2 ? cA[2] : cA[3];
        kB = p2 ? cB[3] : cB[2]; gB = p2 ? cB[2] : cB[3];
        dA1 = kA + __shfl_xor_sync(FULLM, gA, 4);
        dB1 = kB + __shfl_xor_sync(FULLM, gB, 4);
    }
    float eA, eB;
    {
        float kA = p3 ? dA1 : dA0, gA = p3 ? dA0 : dA1;
        float kB = p3 ? dB1 : dB0, gB = p3 ? dB0 : dB1;
        eA = kA + __shfl_xor_sync(FULLM, gA, 8);
        eB = kB + __shfl_xor_sync(FULLM, gB, 8);
    }
    eA += __shfl_xor_sync(FULLM, eA, 16);
    eB += __shfl_xor_sync(FULLM, eB, 16);
    ra = eA;
    rb = eB;
}

__global__ void __launch_bounds__(256, 2)
caps_routing_kernel(const float* __restrict__ x,   // [64, 2048, 16]
                    const float* __restrict__ W,   // [2048, 16, 32, 16]
                    float* __restrict__ out)       // [64, 2048, 32]
{
    const int r = blockIdx.x;
    const int b_base = blockIdx.y << 5;   // 0 or 32
    const int tid = threadIdx.x;
    const int lane = tid & 31;   // = o
    const int wid = tid >> 5;    // 0..7, warp owns b_loc = wid*4 + {0..3}

    // ---- shared memory ----
    // Ws4[i][cq][o] float4, content = (W[c0],W[c1],W[c2],W[c3]) at (o,i), c=4cq+j.
    // GEMM loads (fixed i,cq) are o-contiguous -> conflict-free 4-phase LDS.128.
    __shared__ float4 Ws4[16 * 4 * 32];      // 32768 B
    __shared__ float2 Xs2[32 * 16];          // Xs2[b][i] = (x,x) duplicated  4096 B
    __shared__ float  Rbuf[8][4][16];        // per-warp per-b route rows     2048 B

    // ---- stage W[r] (32 KB): global c-major float4 (i-quads) -> smem c-quads ----
    {
        const float4* Wg4 = reinterpret_cast<const float4*>(W + (size_t)r * 8192);
        float* WsF = reinterpret_cast<float*>(Ws4);
#pragma unroll
        for (int k = 0; k < 8; k++) {
            int f = tid + k * 256;           // global float4 idx: [c][o][i4]
            float4 v = Wg4[f];
            int c = f >> 7, o = (f >> 2) & 31, i4 = f & 3;
            int base = ((4 * i4) * 128 + (c >> 2) * 32 + o) * 4 + (c & 3);
            WsF[base +    0] = v.x;          // i = 4*i4 + 0
            WsF[base +  512] = v.y;          // i += 1 -> +128 float4 = +512 floats
            WsF[base + 1024] = v.z;
            WsF[base + 1536] = v.w;
        }
    }
    // ---- stage x[b_base..b_base+32, r, :] duplicated into pairs ----
    if (tid < 128) {
        int b_loc = tid >> 2, q = tid & 3;
        const float4* xg4 = reinterpret_cast<const float4*>(
            x + (size_t)(b_base + b_loc) * 32768 + (size_t)r * 16);
        float4 xv = xg4[q];
        float2* xd = &Xs2[b_loc * 16 + q * 4];
        xd[0] = make_float2(xv.x, xv.x);
        xd[1] = make_float2(xv.y, xv.y);
        xd[2] = make_float2(xv.z, xv.z);
        xd[3] = make_float2(xv.w, xv.w);
    }
    __syncthreads();

    // ---- u_hat: S[p][cp] = f32x2 over c-pair (2cp, 2cp+1), b = wid*4+p, lane = o ----
    float2 S[4][8];
#pragma unroll
    for (int p = 0; p < 4; p++)
#pragma unroll
        for (int k = 0; k < 8; k++) S[p][k] = make_float2(0.f, 0.f);

#pragma unroll
    for (int i2 = 0; i2 < 8; i2++) {         // i-pair index
        float2 xa[4], xb[4];
#pragma unroll
        for (int p = 0; p < 4; p++) {
            float4 q = *reinterpret_cast<const float4*>(&Xs2[(wid * 4 + p) * 16 + 2 * i2]);
            xa[p] = make_float2(q.x, q.y);   // (x_i, x_i)
            xb[p] = make_float2(q.z, q.w);   // (x_{i+1}, x_{i+1})
        }
#pragma unroll
        for (int cq = 0; cq < 4; cq++) {
            float4 wA = Ws4[(2 * i2) * 128 + cq * 32 + lane];
            float4 wB = Ws4[(2 * i2 + 1) * 128 + cq * 32 + lane];
            float2 wAlo = make_float2(wA.x, wA.y), wAhi = make_float2(wA.z, wA.w);
            float2 wBlo = make_float2(wB.x, wB.y), wBhi = make_float2(wB.z, wB.w);
#pragma unroll
            for (int p = 0; p < 4; p++) {
                S[p][2 * cq + 0] = ffma2(wAlo, xa[p], S[p][2 * cq + 0]);
                S[p][2 * cq + 1] = ffma2(wAhi, xa[p], S[p][2 * cq + 1]);
                S[p][2 * cq + 0] = ffma2(wBlo, xb[p], S[p][2 * cq + 0]);
                S[p][2 * cq + 1] = ffma2(wBhi, xb[p], S[p][2 * cq + 1]);
            }
        }
    }

    // ---- routing: 4 scalar b-chains. Iter1 softmax(0)=uniform; final b-update dead. ----
    float s[4], bown[4];

    // iteration 1: s[b] = (1/16) * sum_c u[c]
#pragma unroll
    for (int p = 0; p < 4; p++) {
        float2 t = add2(add2(add2(S[p][0], S[p][1]), add2(S[p][2], S[p][3])),
                        add2(add2(S[p][4], S[p][5]), add2(S[p][6], S[p][7])));
        s[p] = (t.x + t.y) * 0.0625f;
    }
    squash4(s);                               // s -> v in place
    tr16_pair(S[0], S[1], s[0], s[1], lane, bown[0], bown[1]);
    tr16_pair(S[2], S[3], s[2], s[3], lane, bown[2], bown[3]);

#pragma unroll
    for (int it = 0; it < 2; it++) {
        // distributed softmax over c (c = lane%16, replicated halves)
        float e0 = __expf(bown[0]), e1 = __expf(bown[1]);
        float e2 = __expf(bown[2]), e3 = __expf(bown[3]);
        float Z0 = e0, Z1 = e1, Z2 = e2, Z3 = e3;
#pragma unroll
        for (int m = 1; m <= 8; m <<= 1) {
            Z0 += __shfl_xor_sync(FULLM, Z0, m);
            Z1 += __shfl_xor_sync(FULLM, Z1, m);
            Z2 += __shfl_xor_sync(FULLM, Z2, m);
            Z3 += __shfl_xor_sync(FULLM, Z3, m);
        }
        float rt0 = e0 * rcp_approx(Z0), rt1 = e1 * rcp_approx(Z1);
        float rt2 = e2 * rcp_approx(Z2), rt3 = e3 * rcp_approx(Z3);

        __syncwarp();
        if (lane < 16) {
            Rbuf[wid][0][lane] = rt0;
            Rbuf[wid][1][lane] = rt1;
            Rbuf[wid][2][lane] = rt2;
            Rbuf[wid][3][lane] = rt3;
        }
        __syncwarp();

        // s[b] = sum_c route[c] * u[c]; routes arrive pre-paired for FFMA2
#pragma unroll
        for (int p = 0; p < 4; p++) {
            const float4* rb = reinterpret_cast<const float4*>(&Rbuf[wid][p][0]);
            float4 q0 = rb[0], q1 = rb[1], q2 = rb[2], q3 = rb[3];
            float2 accA = mul2(make_float2(q0.x, q0.y), S[p][0]);
            float2 accB = mul2(make_float2(q0.z, q0.w), S[p][1]);
            accA = ffma2(make_float2(q1.x, q1.y), S[p][2], accA);
            accB = ffma2(make_float2(q1.z, q1.w), S[p][3], accB);
            accA = ffma2(make_float2(q2.x, q2.y), S[p][4], accA);
            accB = ffma2(make_float2(q2.z, q2.w), S[p][5], accB);
            accA = ffma2(make_float2(q3.x, q3.y), S[p][6], accA);
            accB = ffma2(make_float2(q3.z, q3.w), S[p][7], accB);
            float2 t = add2(accA, accB);
            s[p] = t.x + t.y;
        }

        squash4(s);                           // s -> v

        if (it == 0) {
            float d0, d1, d2, d3;
            tr16_pair(S[0], S[1], s[0], s[1], lane, d0, d1);
            tr16_pair(S[2], S[3], s[2], s[3], lane, d2, d3);
            bown[0] += d0; bown[1] += d1; bown[2] += d2; bown[3] += d3;
        }
    }

    // ---- write v: out[b][r][o] ----
    {
        const int bg = b_base + wid * 4;
        float* o0 = out + (size_t)bg * 65536 + (size_t)r * 32 + lane;
        o0[0 * 65536] = s[0];
        o0[1 * 65536] = s[1];
        o0[2 * 65536] = s[2];
        o0[3 * 65536] = s[3];
    }
}

extern "C" void kernel_launch(void* const* d_in, const int* in_sizes, int n_in,
                              void* d_out, int out_size) {
    const float* x = (const float*)d_in[0];
    const float* W = (const float*)d_in[1];
    // defensive: x is the smaller input (2,097,152 vs 16,777,216 elements)
    if (n_in >= 2 && in_sizes[0] > in_sizes[1]) {
        const float* t = x; x = W; W = t;
    }
    float* out = (float*)d_out;
    dim3 grid(2048, 2);
    caps_routing_kernel<<<grid, 256>>>(x, W, out);
}

// round 6
// speedup vs baseline: 1.6842x; 1.0622x over previous
#include <cuda_runtime.h>

// CapsuleLayer dynamic routing, fully fused. Round 6: R3 base (100.8us) +
// interleaved routing chains with register-streamed transpose-reduce +
// cp.async W staging.
// Shapes: B=64, R=2048, C=16, O=32, I=16. 3 routing iterations.
// Grid: (2048, 2). CTA = 256 threads = 8 warps, owns 32 b's; warp owns 4 b's
// as 2 f32x2 b-pairs. Both pairs' routing chains run instruction-interleaved;
// tr16 tree is streamed subtree-by-subtree to bound live registers.

#define FULLM 0xffffffffu

static __device__ __forceinline__ float2 ffma2(float2 a, float2 b, float2 c) {
    unsigned long long ua = *reinterpret_cast<unsigned long long*>(&a);
    unsigned long long ub = *reinterpret_cast<unsigned long long*>(&b);
    unsigned long long uc = *reinterpret_cast<unsigned long long*>(&c);
    unsigned long long ud;
    asm("fma.rn.f32x2 %0, %1, %2, %3;" : "=l"(ud) : "l"(ua), "l"(ub), "l"(uc));
    return *reinterpret_cast<float2*>(&ud);
}
static __device__ __forceinline__ float2 add2(float2 a, float2 b) {
    unsigned long long ua = *reinterpret_cast<unsigned long long*>(&a);
    unsigned long long ub = *reinterpret_cast<unsigned long long*>(&b);
    unsigned long long ud;
    asm("add.rn.f32x2 %0, %1, %2;" : "=l"(ud) : "l"(ua), "l"(ub));
    return *reinterpret_cast<float2*>(&ud);
}
static __device__ __forceinline__ float2 mul2(float2 a, float2 b) {
    unsigned long long ua = *reinterpret_cast<unsigned long long*>(&a);
    unsigned long long ub = *reinterpret_cast<unsigned long long*>(&b);
    unsigned long long ud;
    asm("mul.rn.f32x2 %0, %1, %2;" : "=l"(ud) : "l"(ua), "l"(ub));
    return *reinterpret_cast<float2*>(&ud);
}
static __device__ __forceinline__ float2 pack2(float x) {
    unsigned long long r;
    asm("mov.b64 %0, {%1, %1};" : "=l"(r) : "f"(x));
    return *reinterpret_cast<float2*>(&r);
}
static __device__ __forceinline__ float rcp_approx(float x) {
    float r; asm("rcp.approx.f32 %0, %1;" : "=f"(r) : "f"(x)); return r;
}
static __device__ __forceinline__ float sqrt_approx(float x) {
    float r; asm("sqrt.approx.f32 %0, %1;" : "=f"(r) : "f"(x)); return r;
}
static __device__ __forceinline__ float2 shfl_xor2(float2 v, int m) {
    v.x = __shfl_xor_sync(FULLM, v.x, m);
    v.y = __shfl_xor_sync(FULLM, v.y, m);
    return v;
}
static __device__ __forceinline__ void cp_async16(unsigned dst_smem, const void* src) {
    asm volatile("cp.async.ca.shared.global [%0], [%1], 16;" :: "r"(dst_smem), "l"(src));
}

// squash for BOTH pairs, interleaved: v = s * sqrt(|s|^2)/(1+|s|^2), reduce over o=lanes.
static __device__ __forceinline__ void squash_x2(float2& s0, float2& s1) {
    float2 n0 = mul2(s0, s0);
    float2 n1 = mul2(s1, s1);
#pragma unroll
    for (int m = 16; m >= 1; m >>= 1) {
        n0 = add2(n0, shfl_xor2(n0, m));
        n1 = add2(n1, shfl_xor2(n1, m));
    }
    float f0x = sqrt_approx(n0.x) * rcp_approx(1.0f + n0.x);
    float f0y = sqrt_approx(n0.y) * rcp_approx(1.0f + n0.y);
    float f1x = sqrt_approx(n1.x) * rcp_approx(1.0f + n1.x);
    float f1y = sqrt_approx(n1.y) * rcp_approx(1.0f + n1.y);
    s0 = mul2(s0, make_float2(f0x, f0y));
    s1 = mul2(s1, make_float2(f1x, f1y));
}

// Transpose-reduce for BOTH pairs, interleaved, register-streamed:
// r{q}[lane] = Sum_o S{q}[lane%16][o]*v{q}[o], replicated on both 16-lane halves.
// Levels 1-2 processed as 4 independent subtrees (2 k-slots each) to keep
// live temporaries bounded (~28 regs incl. c arrays) while giving ILP 4.
static __device__ __forceinline__ void tr16_x2s(
    const float2* __restrict__ S0, const float2* __restrict__ S1,
    float2 v0, float2 v1, int lane, float2& r0, float2& r1)
{
    const int p0 = lane & 1, p1 = (lane >> 1) & 1, p2 = (lane >> 2) & 1, p3 = (lane >> 3) & 1;
    float2 c0[4], c1[4];
#pragma unroll
    for (int g = 0; g < 4; g++) {
        // level 1: k = 2g, 2g+1, both chains
        float2 a00, a01, a10, a11;
        {
            int k = 2 * g;
            float2 kA = mul2(p0 ? S0[2 * k + 1] : S0[2 * k], v0);
            float2 gA = mul2(p0 ? S0[2 * k] : S0[2 * k + 1], v0);
            float2 kB = mul2(p0 ? S1[2 * k + 1] : S1[2 * k], v1);
            float2 gB = mul2(p0 ? S1[2 * k] : S1[2 * k + 1], v1);
            a00 = add2(kA, shfl_xor2(gA, 1));
            a10 = add2(kB, shfl_xor2(gB, 1));
            k = 2 * g + 1;
            kA = mul2(p0 ? S0[2 * k + 1] : S0[2 * k], v0);
            gA = mul2(p0 ? S0[2 * k] : S0[2 * k + 1], v0);
            kB = mul2(p0 ? S1[2 * k + 1] : S1[2 * k], v1);
            gB = mul2(p0 ? S1[2 * k] : S1[2 * k + 1], v1);
            a01 = add2(kA, shfl_xor2(gA, 1));
            a11 = add2(kB, shfl_xor2(gB, 1));
        }
        // level 2
        float2 kA = p1 ? a01 : a00, gA = p1 ? a00 : a01;
        float2 kB = p1 ? a11 : a10, gB = p1 ? a10 : a11;
        c0[g] = add2(kA, shfl_xor2(gA, 2));
        c1[g] = add2(kB, shfl_xor2(gB, 2));
    }
    // level 3
    float2 d00, d01, d10, d11;
    {
        float2 kA = p2 ? c0[1] : c0[0], gA = p2 ? c0[0] : c0[1];
        float2 kB = p2 ? c1[1] : c1[0], gB = p2 ? c1[0] : c1[1];
        d00 = add2(kA, shfl_xor2(gA, 4));
        d10 = add2(kB, shfl_xor2(gB, 4));
        kA = p2 ? c0[3] : c0[2]; gA = p2 ? c0[2] : c0[3];
        kB = p2 ? c1[3] : c1[2]; gB = p2 ? c1[2] : c1[3];
        d01 = add2(kA, shfl_xor2(gA, 4));
        d11 = add2(kB, shfl_xor2(gB, 4));
    }
    // level 4
    float2 e0, e1;
    {
        float2 kA = p3 ? d01 : d00, gA = p3 ? d00 : d01;
        float2 kB = p3 ? d11 : d10, gB = p3 ? d10 : d11;
        e0 = add2(kA, shfl_xor2(gA, 8));
        e1 = add2(kB, shfl_xor2(gB, 8));
    }
    // level 5: combine o-halves
    e0 = add2(e0, shfl_xor2(e0, 16));
    e1 = add2(e1, shfl_xor2(e1, 16));
    r0 = e0;
    r1 = e1;
}

__global__ void __launch_bounds__(256, 2)
caps_routing_kernel(const float* __restrict__ x,   // [64, 2048, 16]
                    const float* __restrict__ W,   // [2048, 16, 32, 16]
                    float* __restrict__ out)       // [64, 2048, 32]
{
    const int r = blockIdx.x;
    const int b_base = blockIdx.y << 5;   // 0 or 32
    const int tid = threadIdx.x;
    const int lane = tid & 31;   // = o
    const int wid = tid >> 5;    // 0..7

    __shared__ float4 Ws4[4 * 514];          // [i4][c][o] float4, padded
    __shared__ float2 Xs[16 * 16];           // x b-pairs for this CTA's 32 b's
    __shared__ float2 Rbuf[8][2][16];        // per-warp, per-pair route rows

    // ---- stage W[r] (32 KB) with i4-major transpose via cp.async (16B granule) ----
    {
        const float4* Wg4 = reinterpret_cast<const float4*>(W + (size_t)r * 8192);
        unsigned ws_base = (unsigned)__cvta_generic_to_shared(Ws4);
#pragma unroll
        for (int k = 0; k < 8; k++) {
            int f = tid + k * 256;           // float4 index within [16c][32o][4 i4]
            int c = f >> 7, o = (f >> 2) & 31, i4 = f & 3;
            cp_async16(ws_base + (unsigned)((i4 * 514 + c * 32 + o) * 16), Wg4 + f);
        }
        asm volatile("cp.async.commit_group;" ::: "memory");
    }
    // ---- stage x[b_base : b_base+32, r, :] packed as b-pairs (scalar scatter) ----
    if (tid < 128) {
        int b_loc = tid >> 2, q = tid & 3;
        const float4* xg4 = reinterpret_cast<const float4*>(
            x + (size_t)(b_base + b_loc) * 32768 + (size_t)r * 16);
        float4 xv = xg4[q];
        int p = b_loc >> 1, par = b_loc & 1;
        float* xsf = reinterpret_cast<float*>(Xs);
        xsf[((p * 16 + q * 4 + 0) << 1) + par] = xv.x;
        xsf[((p * 16 + q * 4 + 1) << 1) + par] = xv.y;
        xsf[((p * 16 + q * 4 + 2) << 1) + par] = xv.z;
        xsf[((p * 16 + q * 4 + 3) << 1) + par] = xv.w;
    }
    asm volatile("cp.async.wait_group 0;" ::: "memory");
    __syncthreads();

    // ---- u_hat: u[p][c] = f32x2 over local b-pair (wid*2+p), lane = o ----
    float2 u[2][16];
#pragma unroll
    for (int p = 0; p < 2; p++)
#pragma unroll
        for (int c = 0; c < 16; c++) u[p][c] = make_float2(0.f, 0.f);

#pragma unroll
    for (int i4 = 0; i4 < 4; i4++) {
        float2 xv[2][4];
#pragma unroll
        for (int p = 0; p < 2; p++) {
            const float4* xp = reinterpret_cast<const float4*>(&Xs[(wid * 2 + p) * 16 + i4 * 4]);
            float4 q0 = xp[0];   // uniform (broadcast) LDS.128
            float4 q1 = xp[1];
            xv[p][0] = make_float2(q0.x, q0.y);
            xv[p][1] = make_float2(q0.z, q0.w);
            xv[p][2] = make_float2(q1.x, q1.y);
            xv[p][3] = make_float2(q1.z, q1.w);
        }
#pragma unroll
        for (int c = 0; c < 16; c++) {
            float4 w4 = Ws4[i4 * 514 + c * 32 + lane];
            float2 w0 = pack2(w4.x), w1 = pack2(w4.y), w2 = pack2(w4.z), w3 = pack2(w4.w);
#pragma unroll
            for (int p = 0; p < 2; p++) {
                u[p][c] = ffma2(w0, xv[p][0], u[p][c]);
                u[p][c] = ffma2(w1, xv[p][1], u[p][c]);
                u[p][c] = ffma2(w2, xv[p][2], u[p][c]);
                u[p][c] = ffma2(w3, xv[p][3], u[p][c]);
            }
        }
    }

    // ---- routing: BOTH pairs interleaved. Iter1 softmax(0)=uniform; final b-update dead. ----
    const float2* S0 = u[0];
    const float2* S1 = u[1];

    // iteration 1: route = 1/16 uniform -> s = mean over c
    float2 s0, s1;
    {
        float2 t0[4], t1[4];
#pragma unroll
        for (int k = 0; k < 4; k++) {
            t0[k] = add2(add2(S0[4 * k], S0[4 * k + 1]), add2(S0[4 * k + 2], S0[4 * k + 3]));
            t1[k] = add2(add2(S1[4 * k], S1[4 * k + 1]), add2(S1[4 * k + 2], S1[4 * k + 3]));
        }
        s0 = add2(add2(t0[0], t0[1]), add2(t0[2], t0[3]));
        s1 = add2(add2(t1[0], t1[1]), add2(t1[2], t1[3]));
        const float2 k16 = make_float2(0.0625f, 0.0625f);
        s0 = mul2(s0, k16);
        s1 = mul2(s1, k16);
    }

    squash_x2(s0, s1);                 // s -> v (in place)
    float2 bown0, bown1;
    tr16_x2s(S0, S1, s0, s1, lane, bown0, bown1);

#pragma unroll
    for (int it = 0; it < 2; it++) {
        // distributed softmax over c for both pairs
        float2 e0 = make_float2(__expf(bown0.x), __expf(bown0.y));
        float2 e1 = make_float2(__expf(bown1.x), __expf(bown1.y));
        float2 Z0 = e0, Z1 = e1;
#pragma unroll
        for (int m = 1; m <= 8; m <<= 1) {
            Z0 = add2(Z0, shfl_xor2(Z0, m));
            Z1 = add2(Z1, shfl_xor2(Z1, m));
        }
        float2 route0 = mul2(e0, make_float2(rcp_approx(Z0.x), rcp_approx(Z0.y)));
        float2 route1 = mul2(e1, make_float2(rcp_approx(Z1.x), rcp_approx(Z1.y)));

        __syncwarp();
        if (lane < 16) {
            Rbuf[wid][0][lane] = route0;
            Rbuf[wid][1][lane] = route1;
        }
        __syncwarp();

        // s{q} = sum_c route{q}[c] * S{q}[c]; routes via uniform float4 broadcasts
        const float4* rb0 = reinterpret_cast<const float4*>(&Rbuf[wid][0][0]);
        const float4* rb1 = reinterpret_cast<const float4*>(&Rbuf[wid][1][0]);
        float2 sa0 = make_float2(0.f, 0.f), sb0 = make_float2(0.f, 0.f);
        float2 sa1 = make_float2(0.f, 0.f), sb1 = make_float2(0.f, 0.f);
#pragma unroll
        for (int j = 0; j < 8; j++) {
            float4 t0 = rb0[j];
            float4 t1 = rb1[j];
            sa0 = ffma2(make_float2(t0.x, t0.y), S0[2 * j + 0], sa0);
            sb0 = ffma2(make_float2(t0.z, t0.w), S0[2 * j + 1], sb0);
            sa1 = ffma2(make_float2(t1.x, t1.y), S1[2 * j + 0], sa1);
            sb1 = ffma2(make_float2(t1.z, t1.w), S1[2 * j + 1], sb1);
        }
        s0 = add2(sa0, sb0);
        s1 = add2(sa1, sb1);

        squash_x2(s0, s1);             // s -> v

        if (it == 0) {
            float2 d0, d1;
            tr16_x2s(S0, S1, s0, s1, lane, d0, d1);
            bown0 = add2(bown0, d0);
            bown1 = add2(bown1, d1);
        }
    }

    // ---- write v for all 4 b's: out[b][r][o] ----
    {
        const int bg = b_base + wid * 4;
        float* o0 = out + (size_t)bg * 65536 + (size_t)r * 32 + lane;
        o0[0 * 65536] = s0.x;
        o0[1 * 65536] = s0.y;
        o0[2 * 65536] = s1.x;
        o0[3 * 65536] = s1.y;
    }
}

extern "C" void kernel_launch(void* const* d_in, const int* in_sizes, int n_in,
                              void* d_out, int out_size) {
    const float* x = (const float*)d_in[0];
    const float* W = (const float*)d_in[1];
    // defensive: x is the smaller input (2,097,152 vs 16,777,216 elements)
    if (n_in >= 2 && in_sizes[0] > in_sizes[1]) {
        const float* t = x; x = W; W = t;
    }
    float* out = (float*)d_out;
    dim3 grid(2048, 2);
    caps_routing_kernel<<<grid, 256>>>(x, W, out);
}